// round 3
// baseline (speedup 1.0000x reference)
#include <cuda_runtime.h>
#include <math.h>

// Fixed problem shape
#define NMAX 100000
#define QMAX 256
#define RMAX 401
#define BM   128

// Scratch (device globals — no allocation allowed)
__device__ float g_tableS[NMAX * 64];           // Ws·hidden + Ws_b          (25.6 MB)
__device__ float g_tableR[RMAX * 64];           // Wr·rela
__device__ float g_tableQ[QMAX * 64];           // Wq·q_emb
__device__ float g_tableQR[QMAX * RMAX * 64];   // Wqr·(rela⊙q) + tR + tQ    (26.3 MB)
__device__ float g_agg[NMAX * 64];              // segment-sum accumulator   (25.6 MB)

__device__ __forceinline__ void mac4(float4& a, const float4 x,
                                     const float4 w0, const float4 w1,
                                     const float4 w2, const float4 w3)
{
    a.x = fmaf(x.x, w0.x, fmaf(x.y, w1.x, fmaf(x.z, w2.x, fmaf(x.w, w3.x, a.x))));
    a.y = fmaf(x.x, w0.y, fmaf(x.y, w1.y, fmaf(x.z, w2.y, fmaf(x.w, w3.y, a.y))));
    a.z = fmaf(x.x, w0.z, fmaf(x.y, w1.z, fmaf(x.z, w2.z, fmaf(x.w, w3.z, a.z))));
    a.w = fmaf(x.x, w0.w, fmaf(x.y, w1.w, fmaf(x.z, w2.w, fmaf(x.w, w3.w, a.w))));
}

// -----------------------------------------------------------------------------
// GEMM (NT): out[m,a] = sum_d X[m,d] * W[a,d] (+ bias[a]).  D = A = 64.
// BM=128 rows x 64 cols per block, 512 threads, each does 4 rows x 4 cols.
// ~60 regs -> 2 CTAs x 512 thr = 32 warps/SM (50% occ) to hide LDS latency.
// Optionally zeroes the same row-range of zbuf (fuses agg clear into tS pass).
// -----------------------------------------------------------------------------
__global__ __launch_bounds__(512, 2)
void gemm_nt_kernel(const float* __restrict__ X,
                    const float* __restrict__ W,
                    const float* __restrict__ bias,
                    float* __restrict__ out, int M,
                    float4* __restrict__ zbuf)
{
    __shared__ float Wt[64 * 64];     // Wt[d*64 + a] = W[a*64 + d]
    __shared__ float Xs[BM * 64];
    const int tid = threadIdx.x;
    const int m0 = blockIdx.x * BM;

    #pragma unroll
    for (int i = tid; i < 4096; i += 512)
        Wt[i] = W[((i & 63) << 6) | (i >> 6)];

    #pragma unroll
    for (int i = tid; i < BM * 16; i += 512) {
        int row = i >> 4;
        float4 v = make_float4(0.f, 0.f, 0.f, 0.f);
        if (m0 + row < M) v = __ldg(&((const float4*)X)[(size_t)(m0 + row) * 16 + (i & 15)]);
        ((float4*)Xs)[i] = v;
    }

    // Fused zero of the aggregation buffer (same row range)
    if (zbuf) {
        #pragma unroll
        for (int i = tid; i < BM * 16; i += 512) {
            int row = i >> 4;
            if (m0 + row < M)
                zbuf[(size_t)(m0 + row) * 16 + (i & 15)] = make_float4(0.f, 0.f, 0.f, 0.f);
        }
    }
    __syncthreads();

    const int a0 = (tid & 15) * 4;
    const int r0 = (tid >> 4) * 4;

    float4 binit = make_float4(0.f, 0.f, 0.f, 0.f);
    if (bias) binit = *(const float4*)&bias[a0];
    float4 acc[4];
    #pragma unroll
    for (int i = 0; i < 4; i++) acc[i] = binit;

    #pragma unroll
    for (int d = 0; d < 64; d += 4) {
        float4 w0 = *(const float4*)&Wt[(d + 0) * 64 + a0];
        float4 w1 = *(const float4*)&Wt[(d + 1) * 64 + a0];
        float4 w2 = *(const float4*)&Wt[(d + 2) * 64 + a0];
        float4 w3 = *(const float4*)&Wt[(d + 3) * 64 + a0];
        #pragma unroll
        for (int i = 0; i < 4; i++) {
            float4 xv = *(const float4*)&Xs[(r0 + i) * 64 + d];
            mac4(acc[i], xv, w0, w1, w2, w3);
        }
    }

    #pragma unroll
    for (int i = 0; i < 4; i++)
        if (m0 + r0 + i < M)
            *(float4*)&out[(size_t)(m0 + r0 + i) * 64 + a0] = acc[i];
}

// -----------------------------------------------------------------------------
// QR GEMM: row p=(q,r): X = q_emb[q] ⊙ rela[r]; out = X·Wqr^T + tR[r] + tQ[q]
// -----------------------------------------------------------------------------
__global__ __launch_bounds__(512, 2)
void gemm_qr_kernel(const float* __restrict__ qe,
                    const float* __restrict__ re,
                    const float* __restrict__ W,
                    const float* __restrict__ tR,
                    const float* __restrict__ tQ,
                    float* __restrict__ out, int M, int R)
{
    __shared__ float Wt[64 * 64];
    __shared__ float Xs[BM * 64];
    const int tid = threadIdx.x;
    const int m0 = blockIdx.x * BM;

    #pragma unroll
    for (int i = tid; i < 4096; i += 512)
        Wt[i] = W[((i & 63) << 6) | (i >> 6)];

    #pragma unroll
    for (int i = tid; i < BM * 16; i += 512) {
        int row = i >> 4, c4 = i & 15;
        float4 v = make_float4(0.f, 0.f, 0.f, 0.f);
        int p = m0 + row;
        if (p < M) {
            int q = p / R;
            int r = p - q * R;
            float4 a = __ldg(&((const float4*)qe)[q * 16 + c4]);
            float4 b = __ldg(&((const float4*)re)[r * 16 + c4]);
            v = make_float4(a.x * b.x, a.y * b.y, a.z * b.z, a.w * b.w);
        }
        ((float4*)Xs)[i] = v;
    }
    __syncthreads();

    const int a0 = (tid & 15) * 4;
    const int r0 = (tid >> 4) * 4;
    float4 acc[4];
    #pragma unroll
    for (int i = 0; i < 4; i++) acc[i] = make_float4(0.f, 0.f, 0.f, 0.f);

    #pragma unroll
    for (int d = 0; d < 64; d += 4) {
        float4 w0 = *(const float4*)&Wt[(d + 0) * 64 + a0];
        float4 w1 = *(const float4*)&Wt[(d + 1) * 64 + a0];
        float4 w2 = *(const float4*)&Wt[(d + 2) * 64 + a0];
        float4 w3 = *(const float4*)&Wt[(d + 3) * 64 + a0];
        #pragma unroll
        for (int i = 0; i < 4; i++) {
            float4 xv = *(const float4*)&Xs[(r0 + i) * 64 + d];
            mac4(acc[i], xv, w0, w1, w2, w3);
        }
    }

    const int ac = a0 >> 2;
    #pragma unroll
    for (int i = 0; i < 4; i++) {
        int p = m0 + r0 + i;
        if (p < M) {
            int q = p / R;
            int r = p - q * R;
            float4 t1 = __ldg(&((const float4*)tR)[r * 16 + ac]);
            float4 t2 = __ldg(&((const float4*)tQ)[q * 16 + ac]);
            float4 v = acc[i];
            v.x += t1.x + t2.x; v.y += t1.y + t2.y;
            v.z += t1.z + t2.z; v.w += t1.w + t2.w;
            *(float4*)&out[(size_t)p * 64 + a0] = v;
        }
    }
}

// -----------------------------------------------------------------------------
// Edge kernel: half-warp (16 lanes) per edge, float4 per lane.
// -----------------------------------------------------------------------------
__global__ __launch_bounds__(256)
void edge_kernel(const int* __restrict__ edges,
                 const float* __restrict__ hidden,
                 const float* __restrict__ rela,
                 const float* __restrict__ wa_W,
                 const float* __restrict__ wa_b,
                 const float* __restrict__ tS,
                 const float* __restrict__ tQR,
                 float* __restrict__ agg,
                 float* __restrict__ alpha_out,
                 int E, int R)
{
    const int t = blockIdx.x * 256 + threadIdx.x;
    const int e = t >> 4;
    if (e >= E) return;
    const int sl = t & 15;

    const int* er = edges + (size_t)e * 6;
    const int q = __ldg(er + 0);
    const int r = __ldg(er + 2);
    const int s = __ldg(er + 4);
    const int o = __ldg(er + 5);

    float4 g   = __ldg(&((const float4*)tS)[(size_t)s * 16 + sl]);
    float4 p2  = __ldg(&((const float4*)tQR)[((size_t)q * R + r) * 16 + sl]);
    float4 hs  = __ldg(&((const float4*)hidden)[(size_t)s * 16 + sl]);
    float4 hr  = __ldg(&((const float4*)rela)[(size_t)r * 16 + sl]);
    float4 wa  = __ldg(&((const float4*)wa_W)[sl]);

    float px = fmaxf(g.x + p2.x, 0.f);
    float py = fmaxf(g.y + p2.y, 0.f);
    float pz = fmaxf(g.z + p2.z, 0.f);
    float pw = fmaxf(g.w + p2.w, 0.f);

    float part = fmaf(px, wa.x, fmaf(py, wa.y, fmaf(pz, wa.z, pw * wa.w)));
    #pragma unroll
    for (int off = 8; off; off >>= 1)
        part += __shfl_xor_sync(0xffffffffu, part, off);

    float alpha = 1.0f / (1.0f + __expf(-(part + __ldg(wa_b))));
    if (sl == 0) alpha_out[e] = alpha;

    float4 m;
    m.x = alpha * hs.x * hr.x;
    m.y = alpha * hs.y * hr.y;
    m.z = alpha * hs.z * hr.z;
    m.w = alpha * hs.w * hr.w;

    float* dst = &agg[(size_t)o * 64 + sl * 4];
    asm volatile("red.global.add.v4.f32 [%0], {%1, %2, %3, %4};"
                 :: "l"(dst), "f"(m.x), "f"(m.y), "f"(m.z), "f"(m.w) : "memory");
}

// -----------------------------------------------------------------------------
extern "C" void kernel_launch(void* const* d_in, const int* in_sizes, int n_in,
                              void* d_out, int out_size)
{
    const float* q_emb  = (const float*)d_in[1];
    const float* rela   = (const float*)d_in[2];
    const float* hidden = (const float*)d_in[3];
    const int*   edges  = (const int*)d_in[4];
    const float* Ws_W   = (const float*)d_in[6];
    const float* Ws_b   = (const float*)d_in[7];
    const float* Wr_W   = (const float*)d_in[8];
    const float* Wq_W   = (const float*)d_in[9];
    const float* Wqr_W  = (const float*)d_in[10];
    const float* wa_W   = (const float*)d_in[11];
    const float* wa_b   = (const float*)d_in[12];
    const float* Wh_W   = (const float*)d_in[13];

    const int Q = in_sizes[0];
    const int R = in_sizes[2] / 64;
    const int N = in_sizes[3] / 64;
    const int E = in_sizes[4] / 6;

    float* out = (float*)d_out;
    float* alpha_out = out + (size_t)N * 64;

    float *tS, *tR, *tQ, *tQR, *agg;
    cudaGetSymbolAddress((void**)&tS,  g_tableS);
    cudaGetSymbolAddress((void**)&tR,  g_tableR);
    cudaGetSymbolAddress((void**)&tQ,  g_tableQ);
    cudaGetSymbolAddress((void**)&tQR, g_tableQR);
    cudaGetSymbolAddress((void**)&agg, g_agg);

    // Small tables first (inputs to the QR fold)
    gemm_nt_kernel<<<(R + BM - 1) / BM, 512>>>(rela,  Wr_W, nullptr, tR, R, nullptr);
    gemm_nt_kernel<<<(Q + BM - 1) / BM, 512>>>(q_emb, Wq_W, nullptr, tQ, Q, nullptr);

    // Big precomputes (tS pass also zeroes agg rows)
    gemm_nt_kernel<<<(N + BM - 1) / BM, 512>>>(hidden, Ws_W, Ws_b, tS, N, (float4*)agg);
    gemm_qr_kernel<<<(Q * R + BM - 1) / BM, 512>>>(q_emb, rela, Wqr_W, tR, tQ,
                                                   tQR, Q * R, R);

    // Per-edge gather/gate/scatter (half-warp per edge)
    edge_kernel<<<(E * 16 + 255) / 256, 256>>>(edges, hidden, rela, wa_W, wa_b,
                                               tS, tQR, agg, alpha_out, E, R);

    // Final projection: hidden_new = agg @ Wh^T
    gemm_nt_kernel<<<(N + BM - 1) / BM, 512>>>(agg, Wh_W, nullptr, out, N, nullptr);
}

// round 4
// speedup vs baseline: 1.0108x; 1.0108x over previous
#include <cuda_runtime.h>
#include <math.h>

// Fixed problem shape
#define NMAX 100000
#define QMAX 256
#define RMAX 401
#define BM   256

typedef unsigned long long u64;

// Scratch (device globals — no allocation allowed)
__device__ float g_tableS[NMAX * 64];           // Ws·hidden + Ws_b          (25.6 MB)
__device__ float g_tableR[RMAX * 64];           // Wr·rela
__device__ float g_tableQ[QMAX * 64];           // Wq·q_emb
__device__ float g_tableQR[QMAX * RMAX * 64];   // Wqr·(rela⊙q) + tR + tQ    (26.3 MB)
__device__ float g_agg[NMAX * 64];              // segment-sum accumulator   (25.6 MB)

// ---- packed f32x2 helpers (sm_103a FFMA2) ----
__device__ __forceinline__ u64 ffma2(u64 a, u64 b, u64 c) {
    u64 d;
    asm("fma.rn.f32x2 %0, %1, %2, %3;" : "=l"(d) : "l"(a), "l"(b), "l"(c));
    return d;
}
__device__ __forceinline__ u64 splat2(float x) {
    u64 d;
    unsigned u = __float_as_uint(x);
    asm("mov.b64 %0, {%1, %1};" : "=l"(d) : "r"(u));
    return d;
}
__device__ __forceinline__ u64 pack2(float lo, float hi) {
    u64 d;
    asm("mov.b64 %0, {%1, %2};" : "=l"(d) : "r"(__float_as_uint(lo)), "r"(__float_as_uint(hi)));
    return d;
}
__device__ __forceinline__ float2 unpack2(u64 v) {
    unsigned lo, hi;
    asm("mov.b64 {%0, %1}, %2;" : "=r"(lo), "=r"(hi) : "l"(v));
    return make_float2(__uint_as_float(lo), __uint_as_float(hi));
}

// Core 8x8 FFMA2 mainloop over smem tiles. acc[i][j] = col-pair j of row i.
__device__ __forceinline__ void mainloop_8x8(const float* __restrict__ Wt,
                                             const float* __restrict__ Xs,
                                             int r0, int a0, u64 acc[8][4])
{
    #pragma unroll
    for (int d = 0; d < 64; d += 4) {
        float4 xv[8];
        #pragma unroll
        for (int i = 0; i < 8; i++)
            xv[i] = *(const float4*)&Xs[(r0 + i) * 64 + d];
        #pragma unroll
        for (int k = 0; k < 4; k++) {
            ulonglong2 wA = *(const ulonglong2*)&Wt[(d + k) * 64 + a0];
            ulonglong2 wB = *(const ulonglong2*)&Wt[(d + k) * 64 + a0 + 4];
            #pragma unroll
            for (int i = 0; i < 8; i++) {
                float xs = (k == 0) ? xv[i].x : (k == 1) ? xv[i].y
                         : (k == 2) ? xv[i].z : xv[i].w;
                u64 s = splat2(xs);
                acc[i][0] = ffma2(s, wA.x, acc[i][0]);
                acc[i][1] = ffma2(s, wA.y, acc[i][1]);
                acc[i][2] = ffma2(s, wB.x, acc[i][2]);
                acc[i][3] = ffma2(s, wB.y, acc[i][3]);
            }
        }
    }
}

// -----------------------------------------------------------------------------
// GEMM (NT): out[m,a] = sum_d X[m,d] * W[a,d] (+ bias[a]).  D = A = 64.
// BM=256 rows/block, 256 threads, 8x8 thread tile, packed f32x2 FMA.
// Optionally zeroes the same row-range of zbuf (fuses agg clear into tS pass).
// -----------------------------------------------------------------------------
__global__ __launch_bounds__(256, 2)
void gemm_nt_kernel(const float* __restrict__ X,
                    const float* __restrict__ W,
                    const float* __restrict__ bias,
                    float* __restrict__ out, int M,
                    float4* __restrict__ zbuf)
{
    extern __shared__ float smem[];
    float* Wt = smem;              // [64][64]  Wt[d*64+a] = W[a*64+d]
    float* Xs = smem + 4096;       // [BM][64]
    const int tid = threadIdx.x;
    const int m0 = blockIdx.x * BM;

    #pragma unroll
    for (int i = tid; i < 4096; i += 256)
        Wt[i] = W[((i & 63) << 6) | (i >> 6)];

    #pragma unroll
    for (int i = tid; i < BM * 16; i += 256) {
        int row = i >> 4;
        float4 v = make_float4(0.f, 0.f, 0.f, 0.f);
        if (m0 + row < M) v = __ldg(&((const float4*)X)[(size_t)(m0 + row) * 16 + (i & 15)]);
        ((float4*)Xs)[i] = v;
    }
    if (zbuf) {
        #pragma unroll
        for (int i = tid; i < BM * 16; i += 256) {
            int row = i >> 4;
            if (m0 + row < M)
                zbuf[(size_t)(m0 + row) * 16 + (i & 15)] = make_float4(0.f, 0.f, 0.f, 0.f);
        }
    }
    __syncthreads();

    const int a0 = (tid & 7) * 8;
    const int r0 = (tid >> 3) * 8;

    u64 acc[8][4];
    {
        u64 b0 = 0, b1 = 0, b2 = 0, b3 = 0;
        if (bias) {
            float4 bA = *(const float4*)&bias[a0];
            float4 bB = *(const float4*)&bias[a0 + 4];
            b0 = pack2(bA.x, bA.y); b1 = pack2(bA.z, bA.w);
            b2 = pack2(bB.x, bB.y); b3 = pack2(bB.z, bB.w);
        }
        #pragma unroll
        for (int i = 0; i < 8; i++) {
            acc[i][0] = b0; acc[i][1] = b1; acc[i][2] = b2; acc[i][3] = b3;
        }
    }

    mainloop_8x8(Wt, Xs, r0, a0, acc);

    #pragma unroll
    for (int i = 0; i < 8; i++) {
        int row = m0 + r0 + i;
        if (row < M) {
            *(ulonglong2*)&out[(size_t)row * 64 + a0]     = make_ulonglong2(acc[i][0], acc[i][1]);
            *(ulonglong2*)&out[(size_t)row * 64 + a0 + 4] = make_ulonglong2(acc[i][2], acc[i][3]);
        }
    }
}

// -----------------------------------------------------------------------------
// QR GEMM: row p=(q,r): X = q_emb[q] ⊙ rela[r]; out = X·Wqr^T + tR[r] + tQ[q]
// -----------------------------------------------------------------------------
__global__ __launch_bounds__(256, 2)
void gemm_qr_kernel(const float* __restrict__ qe,
                    const float* __restrict__ re,
                    const float* __restrict__ W,
                    const float* __restrict__ tR,
                    const float* __restrict__ tQ,
                    float* __restrict__ out, int M, int R)
{
    extern __shared__ float smem[];
    float* Wt = smem;
    float* Xs = smem + 4096;
    const int tid = threadIdx.x;
    const int m0 = blockIdx.x * BM;

    #pragma unroll
    for (int i = tid; i < 4096; i += 256)
        Wt[i] = W[((i & 63) << 6) | (i >> 6)];

    #pragma unroll
    for (int i = tid; i < BM * 16; i += 256) {
        int row = i >> 4, c4 = i & 15;
        float4 v = make_float4(0.f, 0.f, 0.f, 0.f);
        int p = m0 + row;
        if (p < M) {
            int q = p / R;
            int r = p - q * R;
            float4 a = __ldg(&((const float4*)qe)[q * 16 + c4]);
            float4 b = __ldg(&((const float4*)re)[r * 16 + c4]);
            v = make_float4(a.x * b.x, a.y * b.y, a.z * b.z, a.w * b.w);
        }
        ((float4*)Xs)[i] = v;
    }
    __syncthreads();

    const int a0 = (tid & 7) * 8;
    const int r0 = (tid >> 3) * 8;

    u64 acc[8][4];
    #pragma unroll
    for (int i = 0; i < 8; i++)
        acc[i][0] = acc[i][1] = acc[i][2] = acc[i][3] = 0ull;

    mainloop_8x8(Wt, Xs, r0, a0, acc);

    #pragma unroll
    for (int i = 0; i < 8; i++) {
        int p = m0 + r0 + i;
        if (p < M) {
            int q = p / R;
            int r = p - q * R;
            float4 tA = __ldg(&((const float4*)tR)[r * 16 + (a0 >> 2)]);
            float4 tB = __ldg(&((const float4*)tR)[r * 16 + (a0 >> 2) + 1]);
            float4 uA = __ldg(&((const float4*)tQ)[q * 16 + (a0 >> 2)]);
            float4 uB = __ldg(&((const float4*)tQ)[q * 16 + (a0 >> 2) + 1]);
            float2 v0 = unpack2(acc[i][0]);
            float2 v1 = unpack2(acc[i][1]);
            float2 v2 = unpack2(acc[i][2]);
            float2 v3 = unpack2(acc[i][3]);
            float4 oA = make_float4(v0.x + tA.x + uA.x, v0.y + tA.y + uA.y,
                                    v1.x + tA.z + uA.z, v1.y + tA.w + uA.w);
            float4 oB = make_float4(v2.x + tB.x + uB.x, v2.y + tB.y + uB.y,
                                    v3.x + tB.z + uB.z, v3.y + tB.w + uB.w);
            *(float4*)&out[(size_t)p * 64 + a0]     = oA;
            *(float4*)&out[(size_t)p * 64 + a0 + 4] = oB;
        }
    }
}

// -----------------------------------------------------------------------------
// Edge kernel: half-warp (16 lanes) per edge, float4 per lane.
// -----------------------------------------------------------------------------
__global__ __launch_bounds__(256)
void edge_kernel(const int* __restrict__ edges,
                 const float* __restrict__ hidden,
                 const float* __restrict__ rela,
                 const float* __restrict__ wa_W,
                 const float* __restrict__ wa_b,
                 const float* __restrict__ tS,
                 const float* __restrict__ tQR,
                 float* __restrict__ agg,
                 float* __restrict__ alpha_out,
                 int E, int R)
{
    const int t = blockIdx.x * 256 + threadIdx.x;
    const int e = t >> 4;
    if (e >= E) return;
    const int sl = t & 15;

    const int* er = edges + (size_t)e * 6;
    const int q = __ldg(er + 0);
    const int r = __ldg(er + 2);
    const int s = __ldg(er + 4);
    const int o = __ldg(er + 5);

    float4 g   = __ldg(&((const float4*)tS)[(size_t)s * 16 + sl]);
    float4 p2  = __ldg(&((const float4*)tQR)[((size_t)q * R + r) * 16 + sl]);
    float4 hs  = __ldg(&((const float4*)hidden)[(size_t)s * 16 + sl]);
    float4 hr  = __ldg(&((const float4*)rela)[(size_t)r * 16 + sl]);
    float4 wa  = __ldg(&((const float4*)wa_W)[sl]);

    float px = fmaxf(g.x + p2.x, 0.f);
    float py = fmaxf(g.y + p2.y, 0.f);
    float pz = fmaxf(g.z + p2.z, 0.f);
    float pw = fmaxf(g.w + p2.w, 0.f);

    float part = fmaf(px, wa.x, fmaf(py, wa.y, fmaf(pz, wa.z, pw * wa.w)));
    #pragma unroll
    for (int off = 8; off; off >>= 1)
        part += __shfl_xor_sync(0xffffffffu, part, off);

    float alpha = 1.0f / (1.0f + __expf(-(part + __ldg(wa_b))));
    if (sl == 0) alpha_out[e] = alpha;

    float4 m;
    m.x = alpha * hs.x * hr.x;
    m.y = alpha * hs.y * hr.y;
    m.z = alpha * hs.z * hr.z;
    m.w = alpha * hs.w * hr.w;

    float* dst = &agg[(size_t)o * 64 + sl * 4];
    asm volatile("red.global.add.v4.f32 [%0], {%1, %2, %3, %4};"
                 :: "l"(dst), "f"(m.x), "f"(m.y), "f"(m.z), "f"(m.w) : "memory");
}

// -----------------------------------------------------------------------------
extern "C" void kernel_launch(void* const* d_in, const int* in_sizes, int n_in,
                              void* d_out, int out_size)
{
    const float* q_emb  = (const float*)d_in[1];
    const float* rela   = (const float*)d_in[2];
    const float* hidden = (const float*)d_in[3];
    const int*   edges  = (const int*)d_in[4];
    const float* Ws_W   = (const float*)d_in[6];
    const float* Ws_b   = (const float*)d_in[7];
    const float* Wr_W   = (const float*)d_in[8];
    const float* Wq_W   = (const float*)d_in[9];
    const float* Wqr_W  = (const float*)d_in[10];
    const float* wa_W   = (const float*)d_in[11];
    const float* wa_b   = (const float*)d_in[12];
    const float* Wh_W   = (const float*)d_in[13];

    const int Q = in_sizes[0];
    const int R = in_sizes[2] / 64;
    const int N = in_sizes[3] / 64;
    const int E = in_sizes[4] / 6;

    float* out = (float*)d_out;
    float* alpha_out = out + (size_t)N * 64;

    float *tS, *tR, *tQ, *tQR, *agg;
    cudaGetSymbolAddress((void**)&tS,  g_tableS);
    cudaGetSymbolAddress((void**)&tR,  g_tableR);
    cudaGetSymbolAddress((void**)&tQ,  g_tableQ);
    cudaGetSymbolAddress((void**)&tQR, g_tableQR);
    cudaGetSymbolAddress((void**)&agg, g_agg);

    const int SMEM = (4096 + BM * 64) * 4;   // Wt + Xs = 80 KB
    cudaFuncSetAttribute(gemm_nt_kernel, cudaFuncAttributeMaxDynamicSharedMemorySize, SMEM);
    cudaFuncSetAttribute(gemm_qr_kernel, cudaFuncAttributeMaxDynamicSharedMemorySize, SMEM);

    // Small tables first (inputs to the QR fold)
    gemm_nt_kernel<<<(R + BM - 1) / BM, 256, SMEM>>>(rela,  Wr_W, nullptr, tR, R, nullptr);
    gemm_nt_kernel<<<(Q + BM - 1) / BM, 256, SMEM>>>(q_emb, Wq_W, nullptr, tQ, Q, nullptr);

    // Big precomputes (tS pass also zeroes agg rows)
    gemm_nt_kernel<<<(N + BM - 1) / BM, 256, SMEM>>>(hidden, Ws_W, Ws_b, tS, N, (float4*)agg);
    gemm_qr_kernel<<<(Q * R + BM - 1) / BM, 256, SMEM>>>(q_emb, rela, Wqr_W, tR, tQ,
                                                         tQR, Q * R, R);

    // Per-edge gather/gate/scatter (half-warp per edge)
    edge_kernel<<<(E * 16 + 255) / 256, 256>>>(edges, hidden, rela, wa_W, wa_b,
                                               tS, tQR, agg, alpha_out, E, R);

    // Final projection: hidden_new = agg @ Wh^T
    gemm_nt_kernel<<<(N + BM - 1) / BM, 256, SMEM>>>(agg, Wh_W, nullptr, out, N, nullptr);
}